// round 1
// baseline (speedup 1.0000x reference)
#include <cuda_runtime.h>
#include <cstdint>

// Problem constants (match reference_code)
#define U_CNT 100000
#define I_CNT 50000
#define DIM   64
#define N_CNT 150000
#define NNZ_E 1000000

// d_out layout (float32), 86,400,000 elements:
//   [0 .. N*D)                        mean  (user_all ++ item_all)
//   [N*D .. N*D + N*4*D)              stacked      (N, 4, D)
//   [N*D + N*4*D .. N*D + 2*N*4*D)    path_stacked (N, 4, D)
// Key insight: the reference loop never updates `ego`, so stacked slots 1..3
// are identical (= A @ ego) and path slots 1..3 are identical (= R @ ego).

static __device__ __forceinline__ const float4* ego_row(
    const float* __restrict__ ue, const float* __restrict__ ie, int n) {
    return (n < U_CNT)
        ? reinterpret_cast<const float4*>(ue + (size_t)n * DIM)
        : reinterpret_cast<const float4*>(ie + (size_t)(n - U_CNT) * DIM);
}

// Kernel 1: write slot 0 = ego into both stacked tensors, zero slot 1 (atomic target).
__global__ void lgcn_init(const float* __restrict__ ue,
                          const float* __restrict__ ie,
                          float* __restrict__ out) {
    int idx = blockIdx.x * blockDim.x + threadIdx.x;     // over N*D/4
    if (idx >= N_CNT * (DIM / 4)) return;
    int n = idx >> 4;            // DIM/4 == 16
    int q = idx & 15;
    float4 e = __ldg(&ego_row(ue, ie, n)[q]);
    float4 z = make_float4(0.f, 0.f, 0.f, 0.f);
    size_t sbase = (size_t)N_CNT * DIM + (size_t)n * 4 * DIM;
    size_t pbase = sbase + (size_t)N_CNT * 4 * DIM;
    float4* s = reinterpret_cast<float4*>(out + sbase);
    float4* p = reinterpret_cast<float4*>(out + pbase);
    s[q]      = e;   // slot 0
    s[16 + q] = z;   // slot 1 (accumulator)
    p[q]      = e;
    p[16 + q] = z;
}

// Kernel 2: fused SpMM for both adjacency matrices.
// 16 threads per edge; thread handles 4 consecutive feature dims.
// One vectorized reduction (red.global.add.v4.f32) per thread.
__global__ void lgcn_spmm(const float* __restrict__ ue,
                          const float* __restrict__ ie,
                          const int*  __restrict__ a_rows,
                          const int*  __restrict__ a_cols,
                          const float* __restrict__ a_vals,
                          const int*  __restrict__ r_rows,
                          const int*  __restrict__ r_cols,
                          const float* __restrict__ r_vals,
                          float* __restrict__ out) {
    long long t = (long long)blockIdx.x * blockDim.x + threadIdx.x;
    if (t >= 2LL * NNZ_E * 16) return;
    int q = (int)(t & 15);
    long long e = t >> 4;
    int which = (e >= NNZ_E);                 // 0 = adj -> stacked, 1 = radj -> path
    int ei = which ? (int)(e - NNZ_E) : (int)e;

    int   row = which ? __ldg(&r_rows[ei]) : __ldg(&a_rows[ei]);
    int   col = which ? __ldg(&r_cols[ei]) : __ldg(&a_cols[ei]);
    float val = which ? __ldg(&r_vals[ei]) : __ldg(&a_vals[ei]);

    float4 x = __ldg(&ego_row(ue, ie, col)[q]);
    float4 c = make_float4(val * x.x, val * x.y, val * x.z, val * x.w);

    // destination: slot 1 of (stacked | path), row `row`, dims q*4..q*4+3
    size_t dst = (size_t)N_CNT * DIM
               + (size_t)which * (size_t)N_CNT * 4 * DIM
               + (size_t)row * 4 * DIM + DIM + (size_t)q * 4;
    float* dp = out + dst;
    asm volatile("red.global.add.v4.f32 [%0], {%1, %2, %3, %4};"
                 :: "l"(dp), "f"(c.x), "f"(c.y), "f"(c.z), "f"(c.w)
                 : "memory");
}

// Kernel 3: replicate slot 1 -> slots 2,3 in both tensors; compute mean.
__global__ void lgcn_final(const float* __restrict__ ue,
                           const float* __restrict__ ie,
                           float* __restrict__ out) {
    int idx = blockIdx.x * blockDim.x + threadIdx.x;     // over N*D/4
    if (idx >= N_CNT * (DIM / 4)) return;
    int n = idx >> 4;
    int q = idx & 15;
    size_t sbase = (size_t)N_CNT * DIM + (size_t)n * 4 * DIM;
    size_t pbase = sbase + (size_t)N_CNT * 4 * DIM;
    float4* s = reinterpret_cast<float4*>(out + sbase);
    float4* p = reinterpret_cast<float4*>(out + pbase);

    float4 a = s[16 + q];
    float4 r = p[16 + q];
    s[32 + q] = a;  s[48 + q] = a;
    p[32 + q] = r;  p[48 + q] = r;

    float4 e = __ldg(&ego_row(ue, ie, n)[q]);
    float4 m = make_float4((e.x + 3.f * a.x) * 0.25f,
                           (e.y + 3.f * a.y) * 0.25f,
                           (e.z + 3.f * a.z) * 0.25f,
                           (e.w + 3.f * a.w) * 0.25f);
    reinterpret_cast<float4*>(out)[(size_t)n * 16 + q] = m;
}

extern "C" void kernel_launch(void* const* d_in, const int* in_sizes, int n_in,
                              void* d_out, int out_size) {
    const float* ue     = (const float*)d_in[0];
    const float* ie     = (const float*)d_in[1];
    const int*   a_rows = (const int*)  d_in[2];
    const int*   a_cols = (const int*)  d_in[3];
    const float* a_vals = (const float*)d_in[4];
    const int*   r_rows = (const int*)  d_in[5];
    const int*   r_cols = (const int*)  d_in[6];
    const float* r_vals = (const float*)d_in[7];
    float* out = (float*)d_out;

    const int nd4 = N_CNT * (DIM / 4);                    // 2.4M threads
    lgcn_init<<<(nd4 + 255) / 256, 256>>>(ue, ie, out);

    const long long edge_threads = 2LL * NNZ_E * 16;      // 32M threads
    lgcn_spmm<<<(int)((edge_threads + 255) / 256), 256>>>(
        ue, ie, a_rows, a_cols, a_vals, r_rows, r_cols, r_vals, out);

    lgcn_final<<<(nd4 + 255) / 256, 256>>>(ue, ie, out);
}